// round 2
// baseline (speedup 1.0000x reference)
#include <cuda_runtime.h>
#include <cuda_bf16.h>
#include <cstdint>

// Problem constants
#define BB    4
#define HH    8
#define SS    2048
#define DD    512
#define HD    64           // head dim
#define BH    (BB*HH)      // 32
#define TK    10           // top_k = min(S//2, 10)

// Scratch: Q/K/V in [bh][s][hd] layout, fp32
__device__ float g_Q[(size_t)BH * SS * HD];
__device__ float g_K[(size_t)BH * SS * HD];
__device__ float g_V[(size_t)BH * SS * HD];

// ---------------------------------------------------------------------------
// Kernel 1: QKV projection.  y[m,n] = sum_k x[m,k]*W[n,k] + b[n]
// (torch Linear: x @ W.T + b).  M=8192, N=512, K=512, three weight sets via
// blockIdx.z.  Classic 128x128x8 register-tiled fp32 GEMM, 8x8 micro-tile.
// ---------------------------------------------------------------------------
#define BM 128
#define BN 128
#define BK 8

__global__ __launch_bounds__(256)
void qkv_gemm(const float* __restrict__ x,
              const float* __restrict__ Wq, const float* __restrict__ bq,
              const float* __restrict__ Wk, const float* __restrict__ bk,
              const float* __restrict__ Wv, const float* __restrict__ bv)
{
    __shared__ float As[BK][BM];
    __shared__ float Bs[BK][BN];

    const int z = blockIdx.z;
    const float* W    = (z == 0) ? Wq : (z == 1) ? Wk : Wv;
    const float* bias = (z == 0) ? bq : (z == 1) ? bk : bv;
    float* dst        = (z == 0) ? g_Q : (z == 1) ? g_K : g_V;

    const int m0 = blockIdx.x * BM;
    const int n0 = blockIdx.y * BN;
    const int t  = threadIdx.x;
    const int tx = t & 15;       // n direction
    const int ty = t >> 4;       // m direction

    const int lrow = t >> 1;         // 0..127
    const int lcg  = (t & 1) * 4;    // 0 or 4

    float acc[8][8];
#pragma unroll
    for (int i = 0; i < 8; i++)
#pragma unroll
        for (int j = 0; j < 8; j++) acc[i][j] = 0.f;

    for (int k0 = 0; k0 < DD; k0 += BK) {
        float4 av = *(const float4*)(x + (size_t)(m0 + lrow) * DD + k0 + lcg);
        float4 wv = *(const float4*)(W + (size_t)(n0 + lrow) * DD + k0 + lcg);
        As[lcg + 0][lrow] = av.x; As[lcg + 1][lrow] = av.y;
        As[lcg + 2][lrow] = av.z; As[lcg + 3][lrow] = av.w;
        Bs[lcg + 0][lrow] = wv.x; Bs[lcg + 1][lrow] = wv.y;
        Bs[lcg + 2][lrow] = wv.z; Bs[lcg + 3][lrow] = wv.w;
        __syncthreads();

#pragma unroll
        for (int kk = 0; kk < BK; kk++) {
            float a[8], b8[8];
            *(float4*)(a)     = *(const float4*)&As[kk][ty * 8];
            *(float4*)(a + 4) = *(const float4*)&As[kk][ty * 8 + 4];
            *(float4*)(b8)    = *(const float4*)&Bs[kk][tx * 8];
            *(float4*)(b8 + 4)= *(const float4*)&Bs[kk][tx * 8 + 4];
#pragma unroll
            for (int i = 0; i < 8; i++)
#pragma unroll
                for (int j = 0; j < 8; j++) acc[i][j] += a[i] * b8[j];
        }
        __syncthreads();
    }

    // Epilogue: add bias, scatter into [bh][s][hd]
#pragma unroll
    for (int i = 0; i < 8; i++) {
        int m = m0 + ty * 8 + i;
        int b = m >> 11;          // m / 2048
        int s = m & (SS - 1);
#pragma unroll
        for (int j = 0; j < 8; j++) {
            int n  = n0 + tx * 8 + j;
            int h  = n >> 6;      // n / 64
            int dh = n & (HD - 1);
            dst[((size_t)(b * HH + h) * SS + s) * HD + dh] = acc[i][j] + bias[n];
        }
    }
}

// ---------------------------------------------------------------------------
// Kernel 2: fused scores GEMM + streaming top-10 + softmax + outputs.
// Block = 256 threads, handles 32 queries of one (b,h).  Keys processed in
// chunks of 256: register-tiled 32x256x64 fp32 GEMM (8x4 micro-tile) into
// smem, then 8 warps (4 queries each) stream chunk scores into per-lane
// sorted top-10 lists.  Finally: warp-merge -> exact top-10 -> 10-way
// softmax -> full attn-row write (float4) + sparse context gather.
// ---------------------------------------------------------------------------
#define QB 32
#define CK 256
#define NCHUNK (SS / CK)
#define KT_STRIDE 260                 // padded row for conflict-free frags

#define SM_QT 0                        // [64][QB]
#define SM_KT (64 * QB)                // [64][KT_STRIDE]
#define SM_SC (SM_KT + 64 * KT_STRIDE) // [QB][CK]
#define SMEM_FLOATS (SM_SC + QB * CK)  // 26880 floats = 107520 B

__device__ __forceinline__ bool gt_pair(float a, int ia, float b, int ib) {
    // "a ranks strictly above b": higher value, ties -> smaller index (lax.top_k)
    return (a > b) || (a == b && ia < ib);
}

__device__ __forceinline__ void topk_insert(float (&v)[TK], int (&id)[TK],
                                            float nv, int ni) {
    // v sorted ascending by rank: v[0] worst, v[9] best
    if (gt_pair(nv, ni, v[0], id[0])) {
        v[0] = nv; id[0] = ni;
#pragma unroll
        for (int j = 0; j < TK - 1; j++) {
            if (gt_pair(v[j], id[j], v[j + 1], id[j + 1])) {
                float tv = v[j]; v[j] = v[j + 1]; v[j + 1] = tv;
                int   ti = id[j]; id[j] = id[j + 1]; id[j + 1] = ti;
            }
        }
    }
}

__device__ __forceinline__ void finalize_query(float (&vals)[TK], int (&ids)[TK],
                                               int bh, int q,
                                               float* __restrict__ out_ctx,
                                               float* __restrict__ out_attn,
                                               int lane)
{
    // Warp-merge 32 per-lane sorted lists into the global top-10 (descending).
    float tv[TK]; int ti[TK];
#pragma unroll
    for (int n = 0; n < TK; n++) {
        float v = vals[TK - 1]; int id = ids[TK - 1];
#pragma unroll
        for (int off = 16; off > 0; off >>= 1) {
            float ov = __shfl_xor_sync(0xffffffffu, v, off);
            int   oi = __shfl_xor_sync(0xffffffffu, id, off);
            if (gt_pair(ov, oi, v, id)) { v = ov; id = oi; }
        }
        tv[n] = v; ti[n] = id;
        if (ids[TK - 1] == id) {       // this lane owned the winner: pop it
#pragma unroll
            for (int j = TK - 1; j > 0; j--) { vals[j] = vals[j - 1]; ids[j] = ids[j - 1]; }
            vals[0] = -3.402823466e38f; ids[0] = 0x7fffffff;
        }
    }

    // Softmax over the 10 survivors (everything else underflows to exact 0)
    float m = tv[0];
    float w[TK]; float ssum = 0.f;
#pragma unroll
    for (int n = 0; n < TK; n++) { w[n] = expf(tv[n] - m); ssum += w[n]; }
    float inv = 1.0f / ssum;
#pragma unroll
    for (int n = 0; n < TK; n++) w[n] *= inv;

    // Write the full attn row (2048 floats): each lane owns 64 contiguous keys
    float* row = out_attn + ((size_t)bh * SS + q) * SS;
#pragma unroll
    for (int c = 0; c < 16; c++) {
        int k0 = lane * 64 + c * 4;
        float4 o = make_float4(0.f, 0.f, 0.f, 0.f);
#pragma unroll
        for (int n = 0; n < TK; n++) {
            int rel = ti[n] - k0;
            if (rel == 0) o.x = w[n];
            else if (rel == 1) o.y = w[n];
            else if (rel == 2) o.z = w[n];
            else if (rel == 3) o.w = w[n];
        }
        *(float4*)(row + k0) = o;
    }

    // Sparse context: ctx[b, q, h*64 + dim] = sum_n w[n] * V[bh, ti[n], dim]
    const float* Vb = g_V + (size_t)bh * SS * HD;
    int b = bh >> 3, h = bh & 7;
#pragma unroll
    for (int half = 0; half < 2; half++) {
        int dim = lane + half * 32;
        float accv = 0.f;
#pragma unroll
        for (int n = 0; n < TK; n++)
            accv += w[n] * Vb[(size_t)ti[n] * HD + dim];
        out_ctx[((size_t)(b * SS + q)) * DD + h * HD + dim] = accv;
    }
}

__global__ __launch_bounds__(256)
void attn_kernel(float* __restrict__ out)
{
    extern __shared__ float sm[];
    float* Qt = sm + SM_QT;   // [k][q]   stride QB
    float* Kt = sm + SM_KT;   // [k][key] stride KT_STRIDE
    float* Sc = sm + SM_SC;   // [q][key] stride CK

    const int t    = threadIdx.x;
    const int lane = t & 31;
    const int warp = t >> 5;         // 0..7, owns queries warp*4 .. warp*4+3
    const int bh   = blockIdx.y;
    const int q0   = blockIdx.x * QB;

    const float* Qb = g_Q + ((size_t)bh * SS + q0) * HD;
    const float* Kb = g_K + (size_t)bh * SS * HD;

    float* out_ctx  = out;
    float* out_attn = out + (size_t)BB * SS * DD;

    // Stage Q tile, transposed: Qt[k][q].  32 queries x 64 dims.
    {
        int q   = t >> 3;            // 0..31
        int dg8 = (t & 7) * 8;       // 0,8,...,56
        float4 v0 = *(const float4*)(Qb + q * HD + dg8);
        float4 v1 = *(const float4*)(Qb + q * HD + dg8 + 4);
        Qt[(dg8 + 0) * QB + q] = v0.x;
        Qt[(dg8 + 1) * QB + q] = v0.y;
        Qt[(dg8 + 2) * QB + q] = v0.z;
        Qt[(dg8 + 3) * QB + q] = v0.w;
        Qt[(dg8 + 4) * QB + q] = v1.x;
        Qt[(dg8 + 5) * QB + q] = v1.y;
        Qt[(dg8 + 6) * QB + q] = v1.z;
        Qt[(dg8 + 7) * QB + q] = v1.w;
    }

    // Per-warp top-10 lists for 4 queries
    float vals[4][TK]; int ids[4][TK];
#pragma unroll
    for (int ql = 0; ql < 4; ql++)
#pragma unroll
        for (int j = 0; j < TK; j++) {
            vals[ql][j] = -3.402823466e38f; ids[ql][j] = 0x7fffffff;
        }

    const int qg = t >> 6;   // 0..3   query group (8 queries each)
    const int kg = t & 63;   // 0..63  key group   (4 keys each)

    for (int ck = 0; ck < NCHUNK; ck++) {
        const int kbase = ck * CK;

        // Stage K chunk, transposed: Kt[k][key]
#pragma unroll
        for (int i = 0; i < 16; i++) {
            int f4  = t + i * 256;
            int key = f4 >> 4;
            int dg  = (f4 & 15) * 4;
            float4 v = *(const float4*)(Kb + (size_t)(kbase + key) * HD + dg);
            Kt[(dg + 0) * KT_STRIDE + key] = v.x;
            Kt[(dg + 1) * KT_STRIDE + key] = v.y;
            Kt[(dg + 2) * KT_STRIDE + key] = v.z;
            Kt[(dg + 3) * KT_STRIDE + key] = v.w;
        }
        __syncthreads();

        // Register-tiled GEMM: 8 queries x 4 keys per thread
        float acc[8][4];
#pragma unroll
        for (int i = 0; i < 8; i++)
#pragma unroll
            for (int j = 0; j < 4; j++) acc[i][j] = 0.f;

#pragma unroll 4
        for (int k = 0; k < HD; k++) {
            float a8[8], b4[4];
            *(float4*)(a8)     = *(const float4*)(Qt + k * QB + qg * 8);
            *(float4*)(a8 + 4) = *(const float4*)(Qt + k * QB + qg * 8 + 4);
            *(float4*)(b4)     = *(const float4*)(Kt + k * KT_STRIDE + kg * 4);
#pragma unroll
            for (int i = 0; i < 8; i++)
#pragma unroll
                for (int j = 0; j < 4; j++) acc[i][j] += a8[i] * b4[j];
        }

#pragma unroll
        for (int i = 0; i < 8; i++) {
            float4 o = make_float4(acc[i][0] * 0.125f, acc[i][1] * 0.125f,
                                   acc[i][2] * 0.125f, acc[i][3] * 0.125f);
            *(float4*)&Sc[(qg * 8 + i) * CK + kg * 4] = o;   // 1/sqrt(64)
        }
        __syncthreads();

        // Streaming top-10: warp scans its 4 queries' chunk scores
        {
            const int qbase = warp * 4;
#pragma unroll
            for (int ql = 0; ql < 4; ql++)
#pragma unroll
                for (int i = 0; i < 8; i++) {
                    int kl = lane + i * 32;
                    topk_insert(vals[ql], ids[ql],
                                Sc[(qbase + ql) * CK + kl], kbase + kl);
                }
        }
        __syncthreads();
    }

#pragma unroll
    for (int ql = 0; ql < 4; ql++)
        finalize_query(vals[ql], ids[ql], bh, q0 + warp * 4 + ql,
                       out_ctx, out_attn, lane);
}

// ---------------------------------------------------------------------------
// Launch
// ---------------------------------------------------------------------------
extern "C" void kernel_launch(void* const* d_in, const int* in_sizes, int n_in,
                              void* d_out, int out_size)
{
    const float* x  = (const float*)d_in[0];
    const float* Wq = (const float*)d_in[1];
    const float* bq = (const float*)d_in[2];
    const float* Wk = (const float*)d_in[3];
    const float* bk = (const float*)d_in[4];
    const float* Wv = (const float*)d_in[5];
    const float* bv = (const float*)d_in[6];

    qkv_gemm<<<dim3(BB * SS / BM, DD / BN, 3), 256>>>(x, Wq, bq, Wk, bk, Wv, bv);

    size_t smem = (size_t)SMEM_FLOATS * sizeof(float);  // 107,520 B
    cudaFuncSetAttribute(attn_kernel,
                         cudaFuncAttributeMaxDynamicSharedMemorySize, (int)smem);
    attn_kernel<<<dim3(SS / QB, BH), 256, smem>>>((float*)d_out);
}

// round 10
// speedup vs baseline: 1.3147x; 1.3147x over previous
#include <cuda_runtime.h>
#include <cuda_bf16.h>
#include <cstdint>

// Problem constants
#define BB    4
#define HH    8
#define SS    2048
#define DD    512
#define HD    64           // head dim
#define BH    (BB*HH)      // 32
#define TK    10           // top_k = min(S//2, 10)

// Scratch: Q/K/V in [bh][s][hd] layout, fp32
__device__ float g_Q[(size_t)BH * SS * HD];
__device__ float g_K[(size_t)BH * SS * HD];
__device__ float g_V[(size_t)BH * SS * HD];

// ---------------------------------------------------------------------------
// Kernel 1: QKV projection.  y[m,n] = sum_k x[m,k]*W[n,k] + b[n]
// M=8192, N=512, K=512, three weight sets via blockIdx.z.
// 128x128x8 register-tiled fp32 GEMM, 8x8 micro-tile.  ~370us in R2
// (≈ fp32 FFMA roofline) — unchanged.
// ---------------------------------------------------------------------------
#define BM 128
#define BN 128
#define BK 8

__global__ __launch_bounds__(256)
void qkv_gemm(const float* __restrict__ x,
              const float* __restrict__ Wq, const float* __restrict__ bq,
              const float* __restrict__ Wk, const float* __restrict__ bk,
              const float* __restrict__ Wv, const float* __restrict__ bv)
{
    __shared__ float As[BK][BM];
    __shared__ float Bs[BK][BN];

    const int z = blockIdx.z;
    const float* W    = (z == 0) ? Wq : (z == 1) ? Wk : Wv;
    const float* bias = (z == 0) ? bq : (z == 1) ? bk : bv;
    float* dst        = (z == 0) ? g_Q : (z == 1) ? g_K : g_V;

    const int m0 = blockIdx.x * BM;
    const int n0 = blockIdx.y * BN;
    const int t  = threadIdx.x;
    const int tx = t & 15;
    const int ty = t >> 4;

    const int lrow = t >> 1;
    const int lcg  = (t & 1) * 4;

    float acc[8][8];
#pragma unroll
    for (int i = 0; i < 8; i++)
#pragma unroll
        for (int j = 0; j < 8; j++) acc[i][j] = 0.f;

    for (int k0 = 0; k0 < DD; k0 += BK) {
        float4 av = *(const float4*)(x + (size_t)(m0 + lrow) * DD + k0 + lcg);
        float4 wv = *(const float4*)(W + (size_t)(n0 + lrow) * DD + k0 + lcg);
        As[lcg + 0][lrow] = av.x; As[lcg + 1][lrow] = av.y;
        As[lcg + 2][lrow] = av.z; As[lcg + 3][lrow] = av.w;
        Bs[lcg + 0][lrow] = wv.x; Bs[lcg + 1][lrow] = wv.y;
        Bs[lcg + 2][lrow] = wv.z; Bs[lcg + 3][lrow] = wv.w;
        __syncthreads();

#pragma unroll
        for (int kk = 0; kk < BK; kk++) {
            float a[8], b8[8];
            *(float4*)(a)     = *(const float4*)&As[kk][ty * 8];
            *(float4*)(a + 4) = *(const float4*)&As[kk][ty * 8 + 4];
            *(float4*)(b8)    = *(const float4*)&Bs[kk][tx * 8];
            *(float4*)(b8 + 4)= *(const float4*)&Bs[kk][tx * 8 + 4];
#pragma unroll
            for (int i = 0; i < 8; i++)
#pragma unroll
                for (int j = 0; j < 8; j++) acc[i][j] += a[i] * b8[j];
        }
        __syncthreads();
    }

#pragma unroll
    for (int i = 0; i < 8; i++) {
        int m = m0 + ty * 8 + i;
        int b = m >> 11;
        int s = m & (SS - 1);
#pragma unroll
        for (int j = 0; j < 8; j++) {
            int n  = n0 + tx * 8 + j;
            int h  = n >> 6;
            int dh = n & (HD - 1);
            dst[((size_t)(b * HH + h) * SS + s) * HD + dh] = acc[i][j] + bias[n];
        }
    }
}

// ---------------------------------------------------------------------------
// Kernel 2: fused scores GEMM + streaming top-10 + softmax + outputs.
// 512 threads, 32 queries per block.  16 warps x 2 queries (top-k state is
// 40 regs/thread, not 80 -> no spills).  GEMM micro-tile 4x4.
// ---------------------------------------------------------------------------
#define QB 32
#define CK 256
#define NCHUNK (SS / CK)
#define KT_STRIDE 260

#define SM_QT 0                        // [64][QB]
#define SM_KT (64 * QB)                // [64][KT_STRIDE]
#define SM_SC (SM_KT + 64 * KT_STRIDE) // [QB][CK]
#define SMEM_FLOATS (SM_SC + QB * CK)  // 26880 floats = 107520 B

__device__ __forceinline__ bool gt_pair(float a, int ia, float b, int ib) {
    // "a ranks strictly above b": higher value, ties -> smaller index (lax.top_k)
    return (a > b) || (a == b && ia < ib);
}

__device__ __forceinline__ void topk_insert(float (&v)[TK], int (&id)[TK],
                                            float nv, int ni) {
    // v sorted ascending by rank: v[0] worst, v[9] best
    if (gt_pair(nv, ni, v[0], id[0])) {
        v[0] = nv; id[0] = ni;
#pragma unroll
        for (int j = 0; j < TK - 1; j++) {
            if (gt_pair(v[j], id[j], v[j + 1], id[j + 1])) {
                float tv = v[j]; v[j] = v[j + 1]; v[j + 1] = tv;
                int   ti = id[j]; id[j] = id[j + 1]; id[j + 1] = ti;
            }
        }
    }
}

__device__ __forceinline__ void finalize_query(float (&vals)[TK], int (&ids)[TK],
                                               int bh, int q,
                                               float* __restrict__ out_ctx,
                                               float* __restrict__ out_attn,
                                               int lane)
{
    // Warp-merge 32 per-lane sorted lists into the global top-10 (descending).
    float tv[TK]; int ti[TK];
#pragma unroll
    for (int n = 0; n < TK; n++) {
        float v = vals[TK - 1]; int id = ids[TK - 1];
#pragma unroll
        for (int off = 16; off > 0; off >>= 1) {
            float ov = __shfl_xor_sync(0xffffffffu, v, off);
            int   oi = __shfl_xor_sync(0xffffffffu, id, off);
            if (gt_pair(ov, oi, v, id)) { v = ov; id = oi; }
        }
        tv[n] = v; ti[n] = id;
        if (ids[TK - 1] == id) {       // this lane owned the winner: pop it
#pragma unroll
            for (int j = TK - 1; j > 0; j--) { vals[j] = vals[j - 1]; ids[j] = ids[j - 1]; }
            vals[0] = -3.402823466e38f; ids[0] = 0x7fffffff;
        }
    }

    // Softmax over the 10 survivors (everything else underflows to exact 0)
    float m = tv[0];
    float w[TK]; float ssum = 0.f;
#pragma unroll
    for (int n = 0; n < TK; n++) { w[n] = expf(tv[n] - m); ssum += w[n]; }
    float inv = 1.0f / ssum;
#pragma unroll
    for (int n = 0; n < TK; n++) w[n] *= inv;

    // Write the full attn row (2048 floats), lane-consecutive float4 stores
    float4* row4 = (float4*)(out_attn + ((size_t)bh * SS + q) * SS);
#pragma unroll
    for (int c = 0; c < 16; c++) {
        int f  = c * 32 + lane;       // float4 index within the row
        int k0 = f * 4;
        float4 o = make_float4(0.f, 0.f, 0.f, 0.f);
#pragma unroll
        for (int n = 0; n < TK; n++) {
            int rel = ti[n] - k0;
            if (rel == 0) o.x = w[n];
            else if (rel == 1) o.y = w[n];
            else if (rel == 2) o.z = w[n];
            else if (rel == 3) o.w = w[n];
        }
        row4[f] = o;
    }

    // Sparse context: ctx[b, q, h*64 + dim] = sum_n w[n] * V[bh, ti[n], dim]
    const float* Vb = g_V + (size_t)bh * SS * HD;
    int b = bh >> 3, h = bh & 7;
#pragma unroll
    for (int half = 0; half < 2; half++) {
        int dim = lane + half * 32;
        float accv = 0.f;
#pragma unroll
        for (int n = 0; n < TK; n++)
            accv += w[n] * Vb[(size_t)ti[n] * HD + dim];
        out_ctx[((size_t)(b * SS + q)) * DD + h * HD + dim] = accv;
    }
}

__global__ __launch_bounds__(512, 1)
void attn_kernel(float* __restrict__ out)
{
    extern __shared__ float sm[];
    float* Qt = sm + SM_QT;   // [k][q]   stride QB, holds Q * (1/8)
    float* Kt = sm + SM_KT;   // [k][key] stride KT_STRIDE
    float* Sc = sm + SM_SC;   // [q][key] stride CK

    const int t    = threadIdx.x;
    const int lane = t & 31;
    const int warp = t >> 5;         // 0..15, owns queries 2w, 2w+1
    const int bh   = blockIdx.y;
    const int q0   = blockIdx.x * QB;

    const float* Qb = g_Q + ((size_t)bh * SS + q0) * HD;
    const float* Kb = g_K + (size_t)bh * SS * HD;

    float* out_ctx  = out;
    float* out_attn = out + (size_t)BB * SS * DD;

    // Stage Q tile, transposed & pre-scaled by 1/sqrt(64): Qt[k][q]
    {
        int q  = t >> 4;             // 0..31
        int dg = (t & 15) * 4;       // 0..60
        float4 v = *(const float4*)(Qb + q * HD + dg);
        Qt[(dg + 0) * QB + q] = v.x * 0.125f;
        Qt[(dg + 1) * QB + q] = v.y * 0.125f;
        Qt[(dg + 2) * QB + q] = v.z * 0.125f;
        Qt[(dg + 3) * QB + q] = v.w * 0.125f;
    }

    // Per-warp top-10 lists for 2 queries (40 regs)
    float vals[2][TK]; int ids[2][TK];
#pragma unroll
    for (int ql = 0; ql < 2; ql++)
#pragma unroll
        for (int j = 0; j < TK; j++) {
            vals[ql][j] = -3.402823466e38f; ids[ql][j] = 0x7fffffff;
        }

    const int qg = t >> 6;   // 0..7   query group (4 queries each)
    const int kg = t & 63;   // 0..63  key group   (4 keys each)

    for (int ck = 0; ck < NCHUNK; ck++) {
        const int kbase = ck * CK;

        // Stage K chunk, transposed: Kt[k][key].  Thread owns one key-half:
        // 2-way store conflicts only; global reads L1/L2-friendly.
        {
            int key  = t >> 1;           // 0..255
            int half = t & 1;            // 0 or 1 (dims 0..31 / 32..63)
            const float* src = Kb + (size_t)(kbase + key) * HD + half * 32;
            float* dstc = Kt + half * 32 * KT_STRIDE + key;
#pragma unroll
            for (int i = 0; i < 8; i++) {
                float4 v = *(const float4*)(src + i * 4);
                dstc[(i * 4 + 0) * KT_STRIDE] = v.x;
                dstc[(i * 4 + 1) * KT_STRIDE] = v.y;
                dstc[(i * 4 + 2) * KT_STRIDE] = v.z;
                dstc[(i * 4 + 3) * KT_STRIDE] = v.w;
            }
        }
        __syncthreads();

        // Register-tiled GEMM: 4 queries x 4 keys per thread
        float acc[4][4];
#pragma unroll
        for (int i = 0; i < 4; i++)
#pragma unroll
            for (int j = 0; j < 4; j++) acc[i][j] = 0.f;

#pragma unroll 8
        for (int k = 0; k < HD; k++) {
            float a4[4], b4[4];
            *(float4*)(a4) = *(const float4*)(Qt + k * QB + qg * 4);
            *(float4*)(b4) = *(const float4*)(Kt + k * KT_STRIDE + kg * 4);
#pragma unroll
            for (int i = 0; i < 4; i++)
#pragma unroll
                for (int j = 0; j < 4; j++) acc[i][j] += a4[i] * b4[j];
        }

#pragma unroll
        for (int i = 0; i < 4; i++) {
            float4 o = make_float4(acc[i][0], acc[i][1], acc[i][2], acc[i][3]);
            *(float4*)&Sc[(qg * 4 + i) * CK + kg * 4] = o;
        }
        __syncthreads();

        // Streaming top-10: warp scans its 2 queries' chunk scores
        {
            const int qbase = warp * 2;
#pragma unroll
            for (int ql = 0; ql < 2; ql++)
#pragma unroll
                for (int i = 0; i < 8; i++) {
                    int kl = lane + i * 32;
                    topk_insert(vals[ql], ids[ql],
                                Sc[(qbase + ql) * CK + kl], kbase + kl);
                }
        }
        __syncthreads();
    }

#pragma unroll
    for (int ql = 0; ql < 2; ql++)
        finalize_query(vals[ql], ids[ql], bh, q0 + warp * 2 + ql,
                       out_ctx, out_attn, lane);
}

// ---------------------------------------------------------------------------
// Launch
// ---------------------------------------------------------------------------
extern "C" void kernel_launch(void* const* d_in, const int* in_sizes, int n_in,
                              void* d_out, int out_size)
{
    const float* x  = (const float*)d_in[0];
    const float* Wq = (const float*)d_in[1];
    const float* bq = (const float*)d_in[2];
    const float* Wk = (const float*)d_in[3];
    const float* bk = (const float*)d_in[4];
    const float* Wv = (const float*)d_in[5];
    const float* bv = (const float*)d_in[6];

    qkv_gemm<<<dim3(BB * SS / BM, DD / BN, 3), 256>>>(x, Wq, bq, Wk, bk, Wv, bv);

    size_t smem = (size_t)SMEM_FLOATS * sizeof(float);  // 107,520 B
    cudaFuncSetAttribute(attn_kernel,
                         cudaFuncAttributeMaxDynamicSharedMemorySize, (int)smem);
    attn_kernel<<<dim3(SS / QB, BH), 512, smem>>>((float*)d_out);
}